// round 15
// baseline (speedup 1.0000x reference)
#include <cuda_runtime.h>
#include <cuda_bf16.h>
#include <cstdint>

using u32 = unsigned int;
using u64 = unsigned long long;

#define D 128
#define MAXN 50048
#define MAXE 800000
#define SCAN_BLK 256
#define NB_SCAN ((MAXN + SCAN_BLK - 1) / SCAN_BLK)
#define SA 136   // smem row stride in bf16 elems (272B, ldsm conflict-free)

// ---------------------------------------------------------------------------
// Scratch (device globals: no allocation allowed)
__device__ float g_dinv[MAXN];
__device__ float g_gbuf[(size_t)MAXN * D];    // layer-1 GEMM output
__device__ float g_gbuf2[(size_t)MAXN * D];   // layer-2 GEMM output (avoids WAR with gather1.h1)
__device__ int   g_cnt[MAXN];
__device__ int   g_off[MAXN];
__device__ int   g_bsum[NB_SCAN];
__device__ int   g_csr[MAXE];
__device__ int   g_is32;
// Pre-split bf16 activations (A operands), row-major [MAXN][128]
__device__ unsigned short g_xh[(size_t)MAXN * D];
__device__ unsigned short g_xl[(size_t)MAXN * D];
__device__ unsigned short g_hh[(size_t)MAXN * D];
__device__ unsigned short g_hl[(size_t)MAXN * D];
// Pre-transposed, bf16-split weights in SA-strided layout: [n][k] at n*SA+k
__device__ unsigned short g_w1h[128 * SA];
__device__ unsigned short g_w1l[128 * SA];
__device__ unsigned short g_w2h[128 * SA];
__device__ unsigned short g_w2l[128 * SA];

__device__ __forceinline__ int load_idx(const void* ei, size_t pos) {
    if (g_is32) return ((const int*)ei)[pos];
    return (int)((const long long*)ei)[pos];
}

// packed fp32x2 add (sm_100+ baseline PTX)
#define ADD2(o, a, b) asm("add.rn.f32x2 %0, %1, %2;" : "=l"(o) : "l"(a), "l"(b))

__device__ __forceinline__ void cp_async16(u32 saddr, const void* gaddr) {
    asm volatile("cp.async.ca.shared.global [%0], [%1], 16;"
                 :: "r"(saddr), "l"(gaddr));
}

__device__ __forceinline__ void split4(const float* f, uint2& hv, uint2& lv) {
    unsigned short hs[4], ls[4];
#pragma unroll
    for (int p = 0; p < 4; p++) {
        __nv_bfloat16 hb = __float2bfloat16(f[p]);
        __nv_bfloat16 lb = __float2bfloat16(f[p] - __bfloat162float(hb));
        hs[p] = __bfloat16_as_ushort(hb);
        ls[p] = __bfloat16_as_ushort(lb);
    }
    hv = make_uint2((u32)hs[0] | ((u32)hs[1] << 16), (u32)hs[2] | ((u32)hs[3] << 16));
    lv = make_uint2((u32)ls[0] | ((u32)ls[1] << 16), (u32)ls[2] | ((u32)ls[3] << 16));
}

// ---------------------------------------------------------------------------
// X -> bf16 hi/lo split (also zero-pads tail rows up to MAXN).
__global__ void xsplit_kernel(const float* __restrict__ X,
                              unsigned short* xh, unsigned short* xl, int n) {
    int t = blockIdx.x * blockDim.x + threadIdx.x;   // one thread per 4 elems
    if (t >= MAXN * 32) return;
    int row = t >> 5;
    uint2 hv = make_uint2(0u, 0u), lv = make_uint2(0u, 0u);
    if (row < n) {
        float4 v = ((const float4*)X)[t];
        float f[4] = {v.x, v.y, v.z, v.w};
        split4(f, hv, lv);
    }
    ((uint2*)xh)[t] = hv;
    ((uint2*)xl)[t] = lv;
}

// ---------------------------------------------------------------------------
// Branch-B head: edge-dtype detect + cnt zero (gates hist) — small and fast.
__global__ void zero_detect_kernel(const long long* __restrict__ ei, int E,
                                   int* cnt, int n) {
    int i = blockIdx.x * blockDim.x + threadIdx.x;
    if (i == 0) {
        int is32 = 0;
        int m = E < 64 ? E : 64;
        for (int t = 0; t < m; t++) {
            long long v = ei[t];
            if (v < 0 || v >= (long long)n) { is32 = 1; break; }
        }
        g_is32 = is32;
    }
    if (i < n) cnt[i] = 0;
}

// W transpose + bf16 split (SA layout) — off the critical path (default stream).
__global__ void wsplit_kernel(const float* __restrict__ W1,
                              const float* __restrict__ W2,
                              unsigned short* w1h, unsigned short* w1l,
                              unsigned short* w2h, unsigned short* w2l) {
    int i = blockIdx.x * blockDim.x + threadIdx.x;
    if (i >= 2 * 128 * 128) return;
    int which = i >> 14;
    int j = i & 16383;
    int k = j >> 7, nn = j & 127;
    const float* W = which ? W2 : W1;
    float v = W[k * 128 + nn];
    __nv_bfloat16 hb = __float2bfloat16(v);
    __nv_bfloat16 lb = __float2bfloat16(v - __bfloat162float(hb));
    int off = nn * SA + k;
    (which ? w2h : w1h)[off] = __bfloat16_as_ushort(hb);
    (which ? w2l : w1l)[off] = __bfloat16_as_ushort(lb);
}

// ---------------------------------------------------------------------------
__global__ void hist_kernel(const void* __restrict__ ei, int* cnt, int E) {
    int e = blockIdx.x * blockDim.x + threadIdx.x;
    if (e < E) atomicAdd(&cnt[load_idx(ei, (size_t)E + e)], 1);
}

// Block-local exclusive scan over cnt -> off; per-block sums -> bsum; also dinv.
__global__ void scan1_kernel(const int* __restrict__ cnt, int* off, int* bsum,
                             float* dinv, int n) {
    __shared__ int s[SCAN_BLK];
    int i = blockIdx.x * SCAN_BLK + threadIdx.x;
    int v = (i < n) ? cnt[i] : 0;
    if (i < n) dinv[i] = rsqrtf((float)v + 1.0f);   // +1 self-loop
    s[threadIdx.x] = v;
    __syncthreads();
#pragma unroll
    for (int d = 1; d < SCAN_BLK; d <<= 1) {
        int t = (threadIdx.x >= d) ? s[threadIdx.x - d] : 0;
        __syncthreads();
        s[threadIdx.x] += t;
        __syncthreads();
    }
    if (i < n) off[i] = s[threadIdx.x] - v;        // block-local exclusive
    if (threadIdx.x == SCAN_BLK - 1) bsum[blockIdx.x] = s[SCAN_BLK - 1];
}

__global__ void scan2_kernel(int* bsum, int nb) {
    __shared__ int s[SCAN_BLK];
    int v = (threadIdx.x < nb) ? bsum[threadIdx.x] : 0;
    s[threadIdx.x] = v;
    __syncthreads();
#pragma unroll
    for (int d = 1; d < SCAN_BLK; d <<= 1) {
        int t = (threadIdx.x >= d) ? s[threadIdx.x - d] : 0;
        __syncthreads();
        s[threadIdx.x] += t;
        __syncthreads();
    }
    if (threadIdx.x < nb) bsum[threadIdx.x] = s[threadIdx.x] - v;  // exclusive
}

// fill CSR: global pos = local cursor + bsum[block of d]
__global__ void fill_kernel(const void* __restrict__ ei, int* off,
                            const int* __restrict__ bsum, int* csr, int E) {
    int e = blockIdx.x * blockDim.x + threadIdx.x;
    if (e < E) {
        int s = load_idx(ei, (size_t)e);
        int d = load_idx(ei, (size_t)E + e);
        int pos = atomicAdd(&off[d], 1) + bsum[d >> 8];
        csr[pos] = s;
    }
}

// ---------------------------------------------------------------------------
// bf16-split GEMM via mma.sync (HMMA), persistent over tile range [tile0,tile1):
// g[row] = (A[row] @ W) * dinv[row];  acc = Ah@Bh + Ah@Bl + Al@Bh.
#define SM_AH 0
#define SM_AL (64 * SA * 2)
#define SM_WH (2 * 64 * SA * 2)
#define SM_WL (SM_WH + 128 * SA * 2)
#define SM_TOTAL (SM_WL + 128 * SA * 2)

__device__ __forceinline__ u32 smem_u32(const void* p) {
    u32 a;
    asm("{ .reg .u64 t; cvta.to.shared.u64 t, %1; cvt.u32.u64 %0, t; }" : "=r"(a) : "l"(p));
    return a;
}

__device__ __forceinline__ void ldsm4(u32* r, u32 addr) {
    asm volatile("ldmatrix.sync.aligned.m8n8.x4.shared.b16 {%0,%1,%2,%3}, [%4];"
                 : "=r"(r[0]), "=r"(r[1]), "=r"(r[2]), "=r"(r[3]) : "r"(addr));
}

__device__ __forceinline__ void mma16816(float* c, const u32* a, u32 b0, u32 b1) {
    asm volatile(
        "mma.sync.aligned.m16n8k16.row.col.f32.bf16.bf16.f32 "
        "{%0,%1,%2,%3}, {%4,%5,%6,%7}, {%8,%9}, {%0,%1,%2,%3};"
        : "+f"(c[0]), "+f"(c[1]), "+f"(c[2]), "+f"(c[3])
        : "r"(a[0]), "r"(a[1]), "r"(a[2]), "r"(a[3]), "r"(b0), "r"(b1));
}

__global__ __launch_bounds__(256, 2) void gemm_mma_kernel(const unsigned short* __restrict__ Ah,
                                                          const unsigned short* __restrict__ Al,
                                                          const unsigned short* __restrict__ Wh,
                                                          const unsigned short* __restrict__ Wl,
                                                          const float* __restrict__ dinv,
                                                          float* __restrict__ g,
                                                          int n, int tile0, int tile1) {
    extern __shared__ char smem[];
    u32 sbase = smem_u32(smem);
    int tid = threadIdx.x;
    int wid = tid >> 5;
    int lane = tid & 31;
    int wr = wid >> 2;          // warp row group 0..1 (32 rows each)
    int wc = wid & 3;           // warp col group 0..3 (32 cols each)

    // ---- stage W hi/lo ONCE via cp.async (already SA-strided in global) ----
    {
        const char* gh = (const char*)Wh;
        const char* gl = (const char*)Wl;
        for (int i = tid; i < 2176; i += 256) {
            cp_async16(sbase + SM_WH + i * 16, gh + i * 16);
            cp_async16(sbase + SM_WL + i * 16, gl + i * 16);
        }
        asm volatile("cp.async.commit_group;");
    }

    int gq = lane >> 3;
    int gr = lane & 7;
    u32 a_off0 = (u32)(((wr * 32 + (gq & 1) * 8 + gr) * SA + (gq >> 1) * 8) * 2);
    u32 a_off1 = a_off0 + (u32)(16 * SA * 2);
    u32 b_off = (u32)(((wc * 32 + (gq >> 1) * 8 + gr) * SA + (gq & 1) * 8) * 2);

    for (int tile = tile0 + blockIdx.x; tile < tile1; tile += gridDim.x) {
        int row0 = tile * 64;

        // ---- stage A tile hi/lo via cp.async (pre-split bf16 in global) ----
        for (int i = tid; i < 1024; i += 256) {
            int r = i >> 4, c = i & 15;
            size_t gidx = (((size_t)(row0 + r)) << 7) + c * 8;   // elements
            u32 sm_off = (u32)((r * SA + c * 8) * 2);
            cp_async16(sbase + SM_AH + sm_off, Ah + gidx);
            cp_async16(sbase + SM_AL + sm_off, Al + gidx);
        }
        asm volatile("cp.async.commit_group;");
        asm volatile("cp.async.wait_group 0;" ::: "memory");
        __syncthreads();

        // ---- fused mma mainloop ----
        float acc[2][4][4];
#pragma unroll
        for (int a = 0; a < 2; a++)
#pragma unroll
            for (int b = 0; b < 4; b++)
#pragma unroll
                for (int c = 0; c < 4; c++) acc[a][b][c] = 0.f;

#pragma unroll
        for (int kt = 0; kt < 8; kt++) {
            u32 ah[8], al[8], bh[8], bl[8];
            ldsm4(ah,     sbase + SM_AH + a_off0 + kt * 32);
            ldsm4(ah + 4, sbase + SM_AH + a_off1 + kt * 32);
            ldsm4(al,     sbase + SM_AL + a_off0 + kt * 32);
            ldsm4(al + 4, sbase + SM_AL + a_off1 + kt * 32);
            ldsm4(bh,     sbase + SM_WH + b_off + kt * 32);
            ldsm4(bh + 4, sbase + SM_WH + b_off + 16 * SA * 2 + kt * 32);
            ldsm4(bl,     sbase + SM_WL + b_off + kt * 32);
            ldsm4(bl + 4, sbase + SM_WL + b_off + 16 * SA * 2 + kt * 32);

#pragma unroll
            for (int nt = 0; nt < 4; nt++) {
                mma16816(acc[0][nt], ah,     bh[2 * nt], bh[2 * nt + 1]);
                mma16816(acc[1][nt], ah + 4, bh[2 * nt], bh[2 * nt + 1]);
            }
#pragma unroll
            for (int nt = 0; nt < 4; nt++) {
                mma16816(acc[0][nt], ah,     bl[2 * nt], bl[2 * nt + 1]);
                mma16816(acc[1][nt], ah + 4, bl[2 * nt], bl[2 * nt + 1]);
            }
#pragma unroll
            for (int nt = 0; nt < 4; nt++) {
                mma16816(acc[0][nt], al,     bh[2 * nt], bh[2 * nt + 1]);
                mma16816(acc[1][nt], al + 4, bh[2 * nt], bh[2 * nt + 1]);
            }
        }

        // ---- epilogue: scale by dinv[row], store ----
        {
            int q = lane >> 2, p = lane & 3;
#pragma unroll
            for (int mt = 0; mt < 2; mt++) {
                int m0 = row0 + wr * 32 + mt * 16 + q;
                int m1 = m0 + 8;
                float dv0 = (m0 < n) ? dinv[m0] : 0.f;
                float dv1 = (m1 < n) ? dinv[m1] : 0.f;
#pragma unroll
                for (int nt = 0; nt < 4; nt++) {
                    int col = wc * 32 + nt * 8 + p * 2;
                    if (m0 < n)
                        *(float2*)(g + (size_t)m0 * D + col) =
                            make_float2(acc[mt][nt][0] * dv0, acc[mt][nt][1] * dv0);
                    if (m1 < n)
                        *(float2*)(g + (size_t)m1 * D + col) =
                            make_float2(acc[mt][nt][2] * dv1, acc[mt][nt][3] * dv1);
                }
            }
        }
        __syncthreads();   // A smem reads done before next tile overwrites
    }
}

// ---------------------------------------------------------------------------
// Pull aggregation over node range [node0, node1), f32x2-packed accumulate.
// mode=1: relu + write bf16 hi/lo split. mode=0: fp32 out.
__global__ void gather_kernel(const int* __restrict__ csr,
                              const int* __restrict__ off,
                              const int* __restrict__ bsum,
                              const ulonglong2* __restrict__ g,
                              const float* __restrict__ dinv,
                              const float* __restrict__ bias,
                              float4* __restrict__ out,
                              unsigned short* outh, unsigned short* outl,
                              int node0, int node1, int mode) {
    int gt = blockIdx.x * blockDim.x + threadIdx.x;
    int node = node0 + (gt >> 5);
    int lane = gt & 31;
    if (node >= node1) return;

    int end = off[node] + bsum[node >> 8];
    int start = (node > 0) ? (off[node - 1] + bsum[(node - 1) >> 8]) : 0;

    ulonglong2 s = g[(size_t)node * 32 + lane];   // self-loop term
    u64 ax = s.x, ay = s.y;

    int e = start;
    for (; e + 4 <= end; e += 4) {
        int s0 = csr[e], s1 = csr[e + 1], s2 = csr[e + 2], s3 = csr[e + 3];
        ulonglong2 v0 = g[(size_t)s0 * 32 + lane];
        ulonglong2 v1 = g[(size_t)s1 * 32 + lane];
        ulonglong2 v2 = g[(size_t)s2 * 32 + lane];
        ulonglong2 v3 = g[(size_t)s3 * 32 + lane];
        u64 t0, t1;
        ADD2(t0, v0.x, v1.x); ADD2(t1, v2.x, v3.x);
        ADD2(ax, ax, t0);     ADD2(ax, ax, t1);
        ADD2(t0, v0.y, v1.y); ADD2(t1, v2.y, v3.y);
        ADD2(ay, ay, t0);     ADD2(ay, ay, t1);
    }
    for (; e < end; e++) {
        int s2 = csr[e];
        ulonglong2 v = g[(size_t)s2 * 32 + lane];
        ADD2(ax, ax, v.x);
        ADD2(ay, ay, v.y);
    }

    u32 x0, x1, y0, y1;
    asm("mov.b64 {%0,%1}, %2;" : "=r"(x0), "=r"(x1) : "l"(ax));
    asm("mov.b64 {%0,%1}, %2;" : "=r"(y0), "=r"(y1) : "l"(ay));

    float dv = dinv[node];
    float4 bb = ((const float4*)bias)[lane];
    float4 o;
    o.x = __uint_as_float(x0) * dv + bb.x;
    o.y = __uint_as_float(x1) * dv + bb.y;
    o.z = __uint_as_float(y0) * dv + bb.z;
    o.w = __uint_as_float(y1) * dv + bb.w;
    if (mode) {
        o.x = fmaxf(o.x, 0.f); o.y = fmaxf(o.y, 0.f);
        o.z = fmaxf(o.z, 0.f); o.w = fmaxf(o.w, 0.f);
        float f[4] = {o.x, o.y, o.z, o.w};
        uint2 hv, lv;
        split4(f, hv, lv);
        ((uint2*)outh)[(size_t)node * 32 + lane] = hv;
        ((uint2*)outl)[(size_t)node * 32 + lane] = lv;
    } else {
        out[(size_t)node * 32 + lane] = o;
    }
}

// ---------------------------------------------------------------------------
extern "C" void kernel_launch(void* const* d_in, const int* in_sizes, int n_in,
                              void* d_out, int out_size) {
    const float* x  = (const float*)d_in[0];
    const void*  ei = (const void*) d_in[1];
    const float* W1 = (const float*)d_in[2];
    const float* b1 = (const float*)d_in[3];
    const float* W2 = (const float*)d_in[4];
    const float* b2 = (const float*)d_in[5];
    float* out = (float*)d_out;

    int n = in_sizes[0] / D;
    int E = in_sizes[1] / 2;

    float *dinv, *gbuf, *gbuf2;
    int *cnt, *off, *bsum, *csr;
    unsigned short *w1h, *w1l, *w2h, *w2l, *xh, *xl, *hh, *hl;
    cudaGetSymbolAddress((void**)&dinv,  g_dinv);
    cudaGetSymbolAddress((void**)&gbuf,  g_gbuf);
    cudaGetSymbolAddress((void**)&gbuf2, g_gbuf2);
    cudaGetSymbolAddress((void**)&cnt,   g_cnt);
    cudaGetSymbolAddress((void**)&off,   g_off);
    cudaGetSymbolAddress((void**)&bsum,  g_bsum);
    cudaGetSymbolAddress((void**)&csr,   g_csr);
    cudaGetSymbolAddress((void**)&w1h,   g_w1h);
    cudaGetSymbolAddress((void**)&w1l,   g_w1l);
    cudaGetSymbolAddress((void**)&w2h,   g_w2h);
    cudaGetSymbolAddress((void**)&w2l,   g_w2l);
    cudaGetSymbolAddress((void**)&xh,    g_xh);
    cudaGetSymbolAddress((void**)&xl,    g_xl);
    cudaGetSymbolAddress((void**)&hh,    g_hh);
    cudaGetSymbolAddress((void**)&hl,    g_hl);

    static cudaStream_t s1 = nullptr;
    static cudaEvent_t ev_fork = nullptr, ev_ready = nullptr, ev_csr = nullptr,
                       ev_a = nullptr, ev_b = nullptr;
    static int smem_set = 0;
    if (!smem_set) {
        cudaFuncSetAttribute(gemm_mma_kernel,
                             cudaFuncAttributeMaxDynamicSharedMemorySize, SM_TOTAL);
        cudaStreamCreateWithFlags(&s1, cudaStreamNonBlocking);
        cudaEventCreateWithFlags(&ev_fork,  cudaEventDisableTiming);
        cudaEventCreateWithFlags(&ev_ready, cudaEventDisableTiming);
        cudaEventCreateWithFlags(&ev_csr,   cudaEventDisableTiming);
        cudaEventCreateWithFlags(&ev_a,     cudaEventDisableTiming);
        cudaEventCreateWithFlags(&ev_b,     cudaEventDisableTiming);
        smem_set = 1;
    }

    int nb_node = (n + 255) / 256;
    int nb_wsplit = (2 * 128 * 128 + 255) / 256;
    int nb_edge = (E + 255) / 256;
    int nb_scan = (n + SCAN_BLK - 1) / SCAN_BLK;
    int ntiles = (n + 63) / 64;
    int half_tiles = ntiles / 2;
    int n_half = half_tiles * 64;
    int gemm_blocks_full = ntiles < 304 ? ntiles : 304;
    int gemm_blocks_half = half_tiles < 304 ? half_tiles : 304;
    int xsplit_blocks = (MAXN * 32) / 256;

    auto gblk = [](int cnt_nodes) {
        long long t = (long long)cnt_nodes * 32;
        return (int)((t + 255) / 256);
    };

    // ---- fork ----
    cudaEventRecord(ev_fork, 0);
    cudaStreamWaitEvent(s1, ev_fork, 0);

    // Branch B (s1): zero+detect -> hist -> scan1 -> scan2 -> fill
    zero_detect_kernel<<<nb_node, 256, 0, s1>>>((const long long*)ei, E, cnt, n);
    hist_kernel<<<nb_edge, 256, 0, s1>>>(ei, cnt, E);
    scan1_kernel<<<nb_scan, SCAN_BLK, 0, s1>>>(cnt, off, bsum, dinv, n);
    cudaEventRecord(ev_ready, s1);
    scan2_kernel<<<1, SCAN_BLK, 0, s1>>>(bsum, nb_scan);
    fill_kernel<<<nb_edge, 256, 0, s1>>>(ei, off, bsum, csr, E);
    cudaEventRecord(ev_csr, s1);

    // Branch A (default): xsplit + wsplit overlap with branch B head
    xsplit_kernel<<<xsplit_blocks, 256>>>(x, xh, xl, n);
    wsplit_kernel<<<nb_wsplit, 256>>>(W1, W2, w1h, w1l, w2h, w2l);
    // gemm1 needs dinv (scan1); W/X splits ordered on this stream
    cudaStreamWaitEvent(0, ev_ready, 0);
    gemm_mma_kernel<<<gemm_blocks_full, 256, SM_TOTAL>>>(xh, xl, w1h, w1l, dinv,
                                                         gbuf, n, 0, ntiles);
    // gather1 first half (needs CSR)
    cudaStreamWaitEvent(0, ev_csr, 0);
    gather_kernel<<<gblk(n_half), 256>>>(csr, off, bsum, (const ulonglong2*)gbuf,
                                         dinv, b1, nullptr, hh, hl, 0, n_half, 1);
    cudaEventRecord(ev_a, 0);

    // s1: gather1 second half (reads gbuf), overlapped with gemm2.h0 (writes gbuf2)
    cudaStreamWaitEvent(s1, ev_a, 0);
    gather_kernel<<<gblk(n - n_half), 256, 0, s1>>>(csr, off, bsum,
                                                    (const ulonglong2*)gbuf,
                                                    dinv, b1, nullptr, hh, hl,
                                                    n_half, n, 1);
    cudaEventRecord(ev_b, s1);

    // default: gemm2 first half (h rows [0, n_half) ready) -> gbuf2
    gemm_mma_kernel<<<gemm_blocks_half, 256, SM_TOTAL>>>(hh, hl, w2h, w2l, dinv,
                                                         gbuf2, n, 0, half_tiles);
    // gemm2 second half after gather1.h1
    cudaStreamWaitEvent(0, ev_b, 0);
    gemm_mma_kernel<<<gemm_blocks_half, 256, SM_TOTAL>>>(hh, hl, w2h, w2l, dinv,
                                                         gbuf2, n, half_tiles, ntiles);
    // final gather (full range) from gbuf2
    gather_kernel<<<gblk(n), 256>>>(csr, off, bsum, (const ulonglong2*)gbuf2,
                                    dinv, b2, (float4*)out, nullptr, nullptr,
                                    0, n, 0);
}

// round 16
// speedup vs baseline: 1.0355x; 1.0355x over previous
#include <cuda_runtime.h>
#include <cuda_bf16.h>
#include <cstdint>

using u32 = unsigned int;
using u64 = unsigned long long;

#define D 128
#define MAXN 50048
#define MAXE 800000
#define SCAN_BLK 256
#define NB_SCAN ((MAXN + SCAN_BLK - 1) / SCAN_BLK)
#define SA 136   // smem row stride in bf16 elems (272B, ldsm conflict-free)

// ---------------------------------------------------------------------------
// Scratch (device globals: no allocation allowed)
__device__ float g_dinv[MAXN];
__device__ float g_gbuf[(size_t)MAXN * D];
__device__ int   g_cnt[MAXN];
__device__ int   g_off[MAXN];
__device__ int   g_bsum[NB_SCAN];
__device__ int   g_csr[MAXE];
__device__ int   g_is32;
// Pre-split bf16 activations (A operands), row-major [MAXN][128]
__device__ unsigned short g_xh[(size_t)MAXN * D];
__device__ unsigned short g_xl[(size_t)MAXN * D];
__device__ unsigned short g_hh[(size_t)MAXN * D];
__device__ unsigned short g_hl[(size_t)MAXN * D];
// Pre-transposed, bf16-split weights in SA-strided layout: [n][k] at n*SA+k
__device__ unsigned short g_w1h[128 * SA];
__device__ unsigned short g_w1l[128 * SA];
__device__ unsigned short g_w2h[128 * SA];
__device__ unsigned short g_w2l[128 * SA];

__device__ __forceinline__ int load_idx(const void* ei, size_t pos) {
    if (g_is32) return ((const int*)ei)[pos];
    return (int)((const long long*)ei)[pos];
}

// packed fp32x2 add (sm_100+ baseline PTX)
#define ADD2(o, a, b) asm("add.rn.f32x2 %0, %1, %2;" : "=l"(o) : "l"(a), "l"(b))

__device__ __forceinline__ void cp_async16(u32 saddr, const void* gaddr) {
    asm volatile("cp.async.ca.shared.global [%0], [%1], 16;"
                 :: "r"(saddr), "l"(gaddr));
}

__device__ __forceinline__ void split4(const float* f, uint2& hv, uint2& lv) {
    unsigned short hs[4], ls[4];
#pragma unroll
    for (int p = 0; p < 4; p++) {
        __nv_bfloat16 hb = __float2bfloat16(f[p]);
        __nv_bfloat16 lb = __float2bfloat16(f[p] - __bfloat162float(hb));
        hs[p] = __bfloat16_as_ushort(hb);
        ls[p] = __bfloat16_as_ushort(lb);
    }
    hv = make_uint2((u32)hs[0] | ((u32)hs[1] << 16), (u32)hs[2] | ((u32)hs[3] << 16));
    lv = make_uint2((u32)ls[0] | ((u32)ls[1] << 16), (u32)ls[2] | ((u32)ls[3] << 16));
}

// ---------------------------------------------------------------------------
// X -> bf16 hi/lo split (also zero-pads tail rows up to MAXN).
__global__ void xsplit_kernel(const float* __restrict__ X,
                              unsigned short* xh, unsigned short* xl, int n) {
    int t = blockIdx.x * blockDim.x + threadIdx.x;   // one thread per 4 elems
    if (t >= MAXN * 32) return;
    int row = t >> 5;
    uint2 hv = make_uint2(0u, 0u), lv = make_uint2(0u, 0u);
    if (row < n) {
        float4 v = ((const float4*)X)[t];
        float f[4] = {v.x, v.y, v.z, v.w};
        split4(f, hv, lv);
    }
    ((uint2*)xh)[t] = hv;
    ((uint2*)xl)[t] = lv;
}

// ---------------------------------------------------------------------------
// Branch-B head: edge-dtype detect + cnt zero (gates hist) — small and fast.
__global__ void zero_detect_kernel(const long long* __restrict__ ei, int E,
                                   int* cnt, int n) {
    int i = blockIdx.x * blockDim.x + threadIdx.x;
    if (i == 0) {
        int is32 = 0;
        int m = E < 64 ? E : 64;
        for (int t = 0; t < m; t++) {
            long long v = ei[t];
            if (v < 0 || v >= (long long)n) { is32 = 1; break; }
        }
        g_is32 = is32;
    }
    if (i < n) cnt[i] = 0;
}

// W transpose + bf16 split (SA layout) — off the critical path (default stream).
__global__ void wsplit_kernel(const float* __restrict__ W1,
                              const float* __restrict__ W2,
                              unsigned short* w1h, unsigned short* w1l,
                              unsigned short* w2h, unsigned short* w2l) {
    int i = blockIdx.x * blockDim.x + threadIdx.x;
    if (i >= 2 * 128 * 128) return;
    int which = i >> 14;
    int j = i & 16383;
    int k = j >> 7, nn = j & 127;
    const float* W = which ? W2 : W1;
    float v = W[k * 128 + nn];
    __nv_bfloat16 hb = __float2bfloat16(v);
    __nv_bfloat16 lb = __float2bfloat16(v - __bfloat162float(hb));
    int off = nn * SA + k;
    (which ? w2h : w1h)[off] = __bfloat16_as_ushort(hb);
    (which ? w2l : w1l)[off] = __bfloat16_as_ushort(lb);
}

// ---------------------------------------------------------------------------
__global__ void hist_kernel(const void* __restrict__ ei, int* cnt, int E) {
    int e = blockIdx.x * blockDim.x + threadIdx.x;
    if (e < E) atomicAdd(&cnt[load_idx(ei, (size_t)E + e)], 1);
}

// Block-local exclusive scan over cnt -> off; per-block sums -> bsum; also dinv.
__global__ void scan1_kernel(const int* __restrict__ cnt, int* off, int* bsum,
                             float* dinv, int n) {
    __shared__ int s[SCAN_BLK];
    int i = blockIdx.x * SCAN_BLK + threadIdx.x;
    int v = (i < n) ? cnt[i] : 0;
    if (i < n) dinv[i] = rsqrtf((float)v + 1.0f);   // +1 self-loop
    s[threadIdx.x] = v;
    __syncthreads();
#pragma unroll
    for (int d = 1; d < SCAN_BLK; d <<= 1) {
        int t = (threadIdx.x >= d) ? s[threadIdx.x - d] : 0;
        __syncthreads();
        s[threadIdx.x] += t;
        __syncthreads();
    }
    if (i < n) off[i] = s[threadIdx.x] - v;        // block-local exclusive
    if (threadIdx.x == SCAN_BLK - 1) bsum[blockIdx.x] = s[SCAN_BLK - 1];
}

__global__ void scan2_kernel(int* bsum, int nb) {
    __shared__ int s[SCAN_BLK];
    int v = (threadIdx.x < nb) ? bsum[threadIdx.x] : 0;
    s[threadIdx.x] = v;
    __syncthreads();
#pragma unroll
    for (int d = 1; d < SCAN_BLK; d <<= 1) {
        int t = (threadIdx.x >= d) ? s[threadIdx.x - d] : 0;
        __syncthreads();
        s[threadIdx.x] += t;
        __syncthreads();
    }
    if (threadIdx.x < nb) bsum[threadIdx.x] = s[threadIdx.x] - v;  // exclusive
}

// fill CSR: global pos = local cursor + bsum[block of d]
__global__ void fill_kernel(const void* __restrict__ ei, int* off,
                            const int* __restrict__ bsum, int* csr, int E) {
    int e = blockIdx.x * blockDim.x + threadIdx.x;
    if (e < E) {
        int s = load_idx(ei, (size_t)e);
        int d = load_idx(ei, (size_t)E + e);
        int pos = atomicAdd(&off[d], 1) + bsum[d >> 8];
        csr[pos] = s;
    }
}

// ---------------------------------------------------------------------------
// bf16-split GEMM via mma.sync (HMMA), persistent over 64-row tiles:
// g[row] = (A[row] @ W) * dinv[row];  acc = Ah@Bh + Ah@Bl + Al@Bh.
#define SM_AH 0
#define SM_AL (64 * SA * 2)
#define SM_WH (2 * 64 * SA * 2)
#define SM_WL (SM_WH + 128 * SA * 2)
#define SM_TOTAL (SM_WL + 128 * SA * 2)

__device__ __forceinline__ u32 smem_u32(const void* p) {
    u32 a;
    asm("{ .reg .u64 t; cvta.to.shared.u64 t, %1; cvt.u32.u64 %0, t; }" : "=r"(a) : "l"(p));
    return a;
}

__device__ __forceinline__ void ldsm4(u32* r, u32 addr) {
    asm volatile("ldmatrix.sync.aligned.m8n8.x4.shared.b16 {%0,%1,%2,%3}, [%4];"
                 : "=r"(r[0]), "=r"(r[1]), "=r"(r[2]), "=r"(r[3]) : "r"(addr));
}

__device__ __forceinline__ void mma16816(float* c, const u32* a, u32 b0, u32 b1) {
    asm volatile(
        "mma.sync.aligned.m16n8k16.row.col.f32.bf16.bf16.f32 "
        "{%0,%1,%2,%3}, {%4,%5,%6,%7}, {%8,%9}, {%0,%1,%2,%3};"
        : "+f"(c[0]), "+f"(c[1]), "+f"(c[2]), "+f"(c[3])
        : "r"(a[0]), "r"(a[1]), "r"(a[2]), "r"(a[3]), "r"(b0), "r"(b1));
}

__global__ __launch_bounds__(256, 2) void gemm_mma_kernel(const unsigned short* __restrict__ Ah,
                                                          const unsigned short* __restrict__ Al,
                                                          const unsigned short* __restrict__ Wh,
                                                          const unsigned short* __restrict__ Wl,
                                                          const float* __restrict__ dinv,
                                                          float* __restrict__ g,
                                                          int n, int ntiles) {
    extern __shared__ char smem[];
    u32 sbase = smem_u32(smem);
    int tid = threadIdx.x;
    int wid = tid >> 5;
    int lane = tid & 31;
    int wr = wid >> 2;          // warp row group 0..1 (32 rows each)
    int wc = wid & 3;           // warp col group 0..3 (32 cols each)

    // ---- stage W hi/lo ONCE via cp.async (already SA-strided in global) ----
    {
        const char* gh = (const char*)Wh;
        const char* gl = (const char*)Wl;
        for (int i = tid; i < 2176; i += 256) {
            cp_async16(sbase + SM_WH + i * 16, gh + i * 16);
            cp_async16(sbase + SM_WL + i * 16, gl + i * 16);
        }
        asm volatile("cp.async.commit_group;");
    }

    int gq = lane >> 3;
    int gr = lane & 7;
    u32 a_off0 = (u32)(((wr * 32 + (gq & 1) * 8 + gr) * SA + (gq >> 1) * 8) * 2);
    u32 a_off1 = a_off0 + (u32)(16 * SA * 2);
    u32 b_off = (u32)(((wc * 32 + (gq >> 1) * 8 + gr) * SA + (gq & 1) * 8) * 2);

    for (int tile = blockIdx.x; tile < ntiles; tile += gridDim.x) {
        int row0 = tile * 64;

        // ---- stage A tile hi/lo via cp.async (pre-split bf16 in global) ----
        for (int i = tid; i < 1024; i += 256) {
            int r = i >> 4, c = i & 15;
            size_t gidx = (((size_t)(row0 + r)) << 7) + c * 8;   // elements
            u32 sm_off = (u32)((r * SA + c * 8) * 2);
            cp_async16(sbase + SM_AH + sm_off, Ah + gidx);
            cp_async16(sbase + SM_AL + sm_off, Al + gidx);
        }
        asm volatile("cp.async.commit_group;");
        asm volatile("cp.async.wait_group 0;" ::: "memory");
        __syncthreads();

        // ---- fused mma mainloop ----
        float acc[2][4][4];
#pragma unroll
        for (int a = 0; a < 2; a++)
#pragma unroll
            for (int b = 0; b < 4; b++)
#pragma unroll
                for (int c = 0; c < 4; c++) acc[a][b][c] = 0.f;

#pragma unroll
        for (int kt = 0; kt < 8; kt++) {
            u32 ah[8], al[8], bh[8], bl[8];
            ldsm4(ah,     sbase + SM_AH + a_off0 + kt * 32);
            ldsm4(ah + 4, sbase + SM_AH + a_off1 + kt * 32);
            ldsm4(al,     sbase + SM_AL + a_off0 + kt * 32);
            ldsm4(al + 4, sbase + SM_AL + a_off1 + kt * 32);
            ldsm4(bh,     sbase + SM_WH + b_off + kt * 32);
            ldsm4(bh + 4, sbase + SM_WH + b_off + 16 * SA * 2 + kt * 32);
            ldsm4(bl,     sbase + SM_WL + b_off + kt * 32);
            ldsm4(bl + 4, sbase + SM_WL + b_off + 16 * SA * 2 + kt * 32);

#pragma unroll
            for (int nt = 0; nt < 4; nt++) {
                mma16816(acc[0][nt], ah,     bh[2 * nt], bh[2 * nt + 1]);
                mma16816(acc[1][nt], ah + 4, bh[2 * nt], bh[2 * nt + 1]);
            }
#pragma unroll
            for (int nt = 0; nt < 4; nt++) {
                mma16816(acc[0][nt], ah,     bl[2 * nt], bl[2 * nt + 1]);
                mma16816(acc[1][nt], ah + 4, bl[2 * nt], bl[2 * nt + 1]);
            }
#pragma unroll
            for (int nt = 0; nt < 4; nt++) {
                mma16816(acc[0][nt], al,     bh[2 * nt], bh[2 * nt + 1]);
                mma16816(acc[1][nt], al + 4, bh[2 * nt], bh[2 * nt + 1]);
            }
        }

        // ---- epilogue: scale by dinv[row], store ----
        {
            int q = lane >> 2, p = lane & 3;
#pragma unroll
            for (int mt = 0; mt < 2; mt++) {
                int m0 = row0 + wr * 32 + mt * 16 + q;
                int m1 = m0 + 8;
                float dv0 = (m0 < n) ? dinv[m0] : 0.f;
                float dv1 = (m1 < n) ? dinv[m1] : 0.f;
#pragma unroll
                for (int nt = 0; nt < 4; nt++) {
                    int col = wc * 32 + nt * 8 + p * 2;
                    if (m0 < n)
                        *(float2*)(g + (size_t)m0 * D + col) =
                            make_float2(acc[mt][nt][0] * dv0, acc[mt][nt][1] * dv0);
                    if (m1 < n)
                        *(float2*)(g + (size_t)m1 * D + col) =
                            make_float2(acc[mt][nt][2] * dv1, acc[mt][nt][3] * dv1);
                }
            }
        }
        __syncthreads();   // A smem reads done before next tile overwrites
    }
}

// ---------------------------------------------------------------------------
// Pull aggregation, f32x2-packed accumulate. Warp per node, lane owns 16B.
// mode=1: relu + write bf16 hi/lo split. mode=0: fp32 out.
__global__ void gather_kernel(const int* __restrict__ csr,
                              const int* __restrict__ off,
                              const int* __restrict__ bsum,
                              const ulonglong2* __restrict__ g,
                              const float* __restrict__ dinv,
                              const float* __restrict__ bias,
                              float4* __restrict__ out,
                              unsigned short* outh, unsigned short* outl,
                              int n, int mode) {
    int gt = blockIdx.x * blockDim.x + threadIdx.x;
    int node = gt >> 5;
    int lane = gt & 31;
    if (node >= n) return;

    int end = off[node] + bsum[node >> 8];
    int start = (node > 0) ? (off[node - 1] + bsum[(node - 1) >> 8]) : 0;

    ulonglong2 s = g[(size_t)node * 32 + lane];   // self-loop term
    u64 ax = s.x, ay = s.y;

    int e = start;
    for (; e + 4 <= end; e += 4) {
        int s0 = csr[e], s1 = csr[e + 1], s2 = csr[e + 2], s3 = csr[e + 3];
        ulonglong2 v0 = g[(size_t)s0 * 32 + lane];
        ulonglong2 v1 = g[(size_t)s1 * 32 + lane];
        ulonglong2 v2 = g[(size_t)s2 * 32 + lane];
        ulonglong2 v3 = g[(size_t)s3 * 32 + lane];
        u64 t0, t1;
        ADD2(t0, v0.x, v1.x); ADD2(t1, v2.x, v3.x);
        ADD2(ax, ax, t0);     ADD2(ax, ax, t1);
        ADD2(t0, v0.y, v1.y); ADD2(t1, v2.y, v3.y);
        ADD2(ay, ay, t0);     ADD2(ay, ay, t1);
    }
    for (; e < end; e++) {
        int s2 = csr[e];
        ulonglong2 v = g[(size_t)s2 * 32 + lane];
        ADD2(ax, ax, v.x);
        ADD2(ay, ay, v.y);
    }

    u32 x0, x1, y0, y1;
    asm("mov.b64 {%0,%1}, %2;" : "=r"(x0), "=r"(x1) : "l"(ax));
    asm("mov.b64 {%0,%1}, %2;" : "=r"(y0), "=r"(y1) : "l"(ay));

    float dv = dinv[node];
    float4 bb = ((const float4*)bias)[lane];
    float4 o;
    o.x = __uint_as_float(x0) * dv + bb.x;
    o.y = __uint_as_float(x1) * dv + bb.y;
    o.z = __uint_as_float(y0) * dv + bb.z;
    o.w = __uint_as_float(y1) * dv + bb.w;
    if (mode) {
        o.x = fmaxf(o.x, 0.f); o.y = fmaxf(o.y, 0.f);
        o.z = fmaxf(o.z, 0.f); o.w = fmaxf(o.w, 0.f);
        float f[4] = {o.x, o.y, o.z, o.w};
        uint2 hv, lv;
        split4(f, hv, lv);
        ((uint2*)outh)[(size_t)node * 32 + lane] = hv;
        ((uint2*)outl)[(size_t)node * 32 + lane] = lv;
    } else {
        out[(size_t)node * 32 + lane] = o;
    }
}

// ---------------------------------------------------------------------------
extern "C" void kernel_launch(void* const* d_in, const int* in_sizes, int n_in,
                              void* d_out, int out_size) {
    const float* x  = (const float*)d_in[0];
    const void*  ei = (const void*) d_in[1];
    const float* W1 = (const float*)d_in[2];
    const float* b1 = (const float*)d_in[3];
    const float* W2 = (const float*)d_in[4];
    const float* b2 = (const float*)d_in[5];
    float* out = (float*)d_out;

    int n = in_sizes[0] / D;
    int E = in_sizes[1] / 2;

    float *dinv, *gbuf;
    int *cnt, *off, *bsum, *csr;
    unsigned short *w1h, *w1l, *w2h, *w2l, *xh, *xl, *hh, *hl;
    cudaGetSymbolAddress((void**)&dinv, g_dinv);
    cudaGetSymbolAddress((void**)&gbuf, g_gbuf);
    cudaGetSymbolAddress((void**)&cnt,  g_cnt);
    cudaGetSymbolAddress((void**)&off,  g_off);
    cudaGetSymbolAddress((void**)&bsum, g_bsum);
    cudaGetSymbolAddress((void**)&csr,  g_csr);
    cudaGetSymbolAddress((void**)&w1h,  g_w1h);
    cudaGetSymbolAddress((void**)&w1l,  g_w1l);
    cudaGetSymbolAddress((void**)&w2h,  g_w2h);
    cudaGetSymbolAddress((void**)&w2l,  g_w2l);
    cudaGetSymbolAddress((void**)&xh,   g_xh);
    cudaGetSymbolAddress((void**)&xl,   g_xl);
    cudaGetSymbolAddress((void**)&hh,   g_hh);
    cudaGetSymbolAddress((void**)&hl,   g_hl);

    static cudaStream_t s1 = nullptr;
    static cudaEvent_t ev_fork = nullptr, ev_ready = nullptr, ev_csr = nullptr;
    static int smem_set = 0;
    if (!smem_set) {
        cudaFuncSetAttribute(gemm_mma_kernel,
                             cudaFuncAttributeMaxDynamicSharedMemorySize, SM_TOTAL);
        cudaStreamCreateWithFlags(&s1, cudaStreamNonBlocking);
        cudaEventCreateWithFlags(&ev_fork,  cudaEventDisableTiming);
        cudaEventCreateWithFlags(&ev_ready, cudaEventDisableTiming);
        cudaEventCreateWithFlags(&ev_csr,   cudaEventDisableTiming);
        smem_set = 1;
    }

    int nb_node = (n + 255) / 256;
    int nb_wsplit = (2 * 128 * 128 + 255) / 256;
    int nb_edge = (E + 255) / 256;
    int nb_scan = (n + SCAN_BLK - 1) / SCAN_BLK;
    int ntiles = (n + 63) / 64;
    int gemm_blocks = 304;               // ~2 CTAs/SM, persistent stride loop
    if (gemm_blocks > ntiles) gemm_blocks = ntiles;
    long long gthreads = (long long)n * 32;
    int gather_blocks = (int)((gthreads + 255) / 256);
    int xsplit_blocks = (MAXN * 32) / 256;

    // ---- fork: branch B (CSR build) on s1, branch A (compute) on default ----
    cudaEventRecord(ev_fork, 0);
    cudaStreamWaitEvent(s1, ev_fork, 0);

    // Branch B (s1): zero+detect -> hist -> scan1 -> scan2 -> fill
    zero_detect_kernel<<<nb_node, 256, 0, s1>>>((const long long*)ei, E, cnt, n);
    hist_kernel<<<nb_edge, 256, 0, s1>>>(ei, cnt, E);
    scan1_kernel<<<nb_scan, SCAN_BLK, 0, s1>>>(cnt, off, bsum, dinv, n);
    cudaEventRecord(ev_ready, s1);
    scan2_kernel<<<1, SCAN_BLK, 0, s1>>>(bsum, nb_scan);
    fill_kernel<<<nb_edge, 256, 0, s1>>>(ei, off, bsum, csr, E);
    cudaEventRecord(ev_csr, s1);

    // Branch A (default): xsplit + wsplit overlap with branch B head
    xsplit_kernel<<<xsplit_blocks, 256>>>(x, xh, xl, n);
    wsplit_kernel<<<nb_wsplit, 256>>>(W1, W2, w1h, w1l, w2h, w2l);
    // gemm1 needs dinv (scan1); W/X splits ordered on this stream
    cudaStreamWaitEvent(0, ev_ready, 0);
    gemm_mma_kernel<<<gemm_blocks, 256, SM_TOTAL>>>(xh, xl, w1h, w1l, dinv, gbuf,
                                                    n, ntiles);
    // gather1 needs the CSR (fill); scan2+fill overlapped with gemm1
    cudaStreamWaitEvent(0, ev_csr, 0);
    gather_kernel<<<gather_blocks, 256>>>(csr, off, bsum, (const ulonglong2*)gbuf,
                                          dinv, b1, nullptr, hh, hl, n, 1);
    gemm_mma_kernel<<<gemm_blocks, 256, SM_TOTAL>>>(hh, hl, w2h, w2l, dinv, gbuf,
                                                    n, ntiles);
    gather_kernel<<<gather_blocks, 256>>>(csr, off, bsum, (const ulonglong2*)gbuf,
                                          dinv, b2, (float4*)out, nullptr, nullptr,
                                          n, 0);
}